// round 10
// baseline (speedup 1.0000x reference)
#include <cuda_runtime.h>
#include <math.h>

#define NN    4096
#define NI_   1024
#define NB    8
#define NT    500
#define NWORD 128          // NN/32
#define SIM_CTAS 128       // 4 batch-pairs x 32 col-blocks (128 cols each)
#define SIM_TPB  256       // 128 E threads + 128 I threads, 1 col/thread, 2 slots

// ---- device scratch ----
__device__ float     g_weff[(size_t)NN * NN];          // 64 MB
__device__ float     g_dff[(size_t)NT * NB * NN];      // 65.5 MB [t][b*N+j]
__device__ unsigned  g_mask[2][2][NB][NWORD];          // [buf][type][batch][word]
__device__ unsigned  g_cntB[NB * 32];                  // per-batch counters (padded)

struct SimConsts {
    float ar[4], ad[4], omad[4], esyn[4];
    float dtt0, dtt1;
};

// ------------------------------------------------------------------
__global__ void init_kernel() {
    int idx = blockIdx.x * blockDim.x + threadIdx.x;
    if (idx < NB * 32) g_cntB[idx] = 0u;
    if (idx < 2 * NB * NWORD) ((unsigned*)g_mask[0])[idx] = 0u;
}

// ------------------------------------------------------------------
__global__ void weff_kernel(const float* __restrict__ W,
                            const float* __restrict__ scal,
                            const int*   __restrict__ ci) {
    int idx = blockIdx.x * 256 + threadIdx.x;          // float4 index
    int e = idx << 2;
    int i = e >> 12;
    int j = e & (NN - 1);
    float4 w = __ldg((const float4*)W + idx);
    int cri = __ldg(&ci[i]) * 2;
    float4 r;
    r.x = __fmul_rn(w.x, __ldg(&scal[cri + __ldg(&ci[j + 0])]));
    r.y = __fmul_rn(w.y, __ldg(&scal[cri + __ldg(&ci[j + 1])]));
    r.z = __fmul_rn(w.z, __ldg(&scal[cri + __ldg(&ci[j + 2])]));
    r.w = __fmul_rn(w.w, __ldg(&scal[cri + __ldg(&ci[j + 3])]));
    ((float4*)g_weff)[idx] = r;
}

// ------------------------------------------------------------------
// FF drive (unchanged).
// ------------------------------------------------------------------
__global__ void ff_kernel(const float* __restrict__ sp,
                          const float* __restrict__ wff,
                          const float* __restrict__ sff,
                          const int*   __restrict__ ciff,
                          const int*   __restrict__ ci) {
    __shared__ int    s_act[NI_];
    __shared__ float2 s_fv[NI_];
    __shared__ int    s_cnt[33];

    const int x   = blockIdx.x;
    const int t   = x >> 3;
    const int b   = x & 7;
    const int tid = threadIdx.x;
    const int lane = tid & 31;
    const int wrp  = tid >> 5;

    bool act[4]; int rnk[4];
#pragma unroll
    for (int r = 0; r < 4; ++r) {
        int i = r * 256 + tid;
        float sv = __ldg(&sp[((size_t)b * NT + t) * NI_ + i]);
        bool a = (sv != 0.0f);
        unsigned bal = __ballot_sync(0xffffffffu, a);
        if (lane == 0) s_cnt[r * 8 + wrp] = __popc(bal);
        act[r] = a;
        rnk[r] = __popc(bal & ((1u << lane) - 1u));
    }
    __syncthreads();
    if (tid == 0) {
        int run = 0;
#pragma unroll
        for (int s = 0; s < 32; ++s) { int c = s_cnt[s]; s_cnt[s] = run; run += c; }
        s_cnt[32] = run;
    }
    __syncthreads();
#pragma unroll
    for (int r = 0; r < 4; ++r) {
        if (act[r]) {
            int i = r * 256 + tid;
            int pos = s_cnt[r * 8 + wrp] + rnk[r];
            s_act[pos] = i << 10;
            int cf = __ldg(&ciff[i]) * 2;
            s_fv[pos] = make_float2(__ldg(&sff[cf]), __ldg(&sff[cf + 1]));
        }
    }
    __syncthreads();
    const int total = s_cnt[32];

    int4 ctq[4];
#pragma unroll
    for (int r = 0; r < 4; ++r) ctq[r] = __ldg((const int4*)ci + tid + 256 * r);

    float4 acc[4];
#pragma unroll
    for (int r = 0; r < 4; ++r) acc[r] = make_float4(0, 0, 0, 0);

    for (int k = 0; k < total; ++k) {
        int roff = s_act[k];
        float2 f = s_fv[k];
#pragma unroll
        for (int r = 0; r < 4; ++r) {
            float4 w4 = __ldg((const float4*)wff + roff + tid + 256 * r);
            acc[r].x = __fadd_rn(acc[r].x, __fmul_rn(w4.x, ctq[r].x ? f.y : f.x));
            acc[r].y = __fadd_rn(acc[r].y, __fmul_rn(w4.y, ctq[r].y ? f.y : f.x));
            acc[r].z = __fadd_rn(acc[r].z, __fmul_rn(w4.z, ctq[r].z ? f.y : f.x));
            acc[r].w = __fadd_rn(acc[r].w, __fmul_rn(w4.w, ctq[r].w ? f.y : f.x));
        }
    }
    size_t o = (size_t)x * (NN / 4);
#pragma unroll
    for (int r = 0; r < 4; ++r) ((float4*)g_dff)[o + tid + 256 * r] = acc[r];
}

// ------------------------------------------------------------------
// scalar gather, depth-16 double buffer (ushort list entries = row i)
// ------------------------------------------------------------------
__device__ __forceinline__ float gather_scalar(const float* __restrict__ Wcol,
                                               const unsigned short* __restrict__ lst,
                                               int tot) {
    float acc = 0.0f;
    float bA[16], bB[16];
#pragma unroll
    for (int u = 0; u < 16; ++u)
        bA[u] = (u < tot) ? __ldg(Wcol + (((int)lst[u]) << 12)) : 0.0f;
    for (int base = 0; base < tot; base += 32) {
#pragma unroll
        for (int u = 0; u < 16; ++u) {
            int k = base + 16 + u;
            bB[u] = (k < tot) ? __ldg(Wcol + (((int)lst[k]) << 12)) : 0.0f;
        }
#pragma unroll
        for (int u = 0; u < 16; ++u) acc = __fadd_rn(acc, bA[u]);
#pragma unroll
        for (int u = 0; u < 16; ++u) {
            int k = base + 32 + u;
            bA[u] = (k < tot) ? __ldg(Wcol + (((int)lst[k]) << 12)) : 0.0f;
        }
#pragma unroll
        for (int u = 0; u < 16; ++u) acc = __fadd_rn(acc, bB[u]);
    }
    return acc;
}

// ------------------------------------------------------------------
// Persistent sim: 2 interleaved batch streams per CTA.
// CTA = (pair p = blockIdx>>5, colblock cb = blockIdx&31): slots
// (bA=p, cb) and (bB=p+4, cb), 128 cols each. 256 threads: E=tid<128
// accumulates E channel + owns membrane state for BOTH slots; I=tid>=128
// accumulates I channel. E warps build batch-A lists / I warps batch-B.
// ------------------------------------------------------------------
__global__ void __launch_bounds__(SIM_TPB, 1)
sim_kernel(const int* __restrict__ ci, float* __restrict__ out, SimConsts C) {
    __shared__ unsigned short s_lstAE[NN], s_lstAI[NN];
    __shared__ unsigned short s_lstBE[NN], s_lstBI[NN];
    __shared__ float s_accIA[128], s_accIB[128];
    __shared__ int   s_wsumA[4], s_wsumB[4];

    const int tid  = threadIdx.x;
    const int lane = tid & 31;
    const int wrp  = tid >> 5;
    const bool isE = (tid < 128);
    const int c    = tid & 127;                    // column within block
    const int cb   = blockIdx.x & 31;
    const int pr   = blockIdx.x >> 5;
    const int bA   = pr;
    const int bB   = pr + 4;
    const int j    = (cb << 7) + c;
    const int myct = __ldg(&ci[j]);

    // builder role: E warps (0-3) -> batch A lists; I warps (4-7) -> batch B
    const int slotW = wrp & 3;
    const int type  = slotW >> 1;
    const int half  = slotW & 1;
    const int bLst  = isE ? bA : bB;

    const float dtt   = myct ? C.dtt1 : C.dtt0;
    const float refst = myct ? 10.0f : 20.0f;
    const float theta = -50.0f, u_reset = -65.0f, e_l = -70.0f, g_l = 10.0f;

    // membrane state for both slots (E threads only use these)
    float vA = e_l, refA = 0, hA0 = 0, hA1 = 0, hA2 = 0, hA3 = 0,
          qA0 = 0, qA1 = 0, qA2 = 0, qA3 = 0;
    float vB = e_l, refB = 0, hB0 = 0, hB1 = 0, hB2 = 0, hB3 = 0,
          qB0 = 0, qB1 = 0, qB2 = 0, qB3 = 0;

    const float* __restrict__ Wcol = g_weff + j;
    float* outA = out + ((size_t)bA * NT) * NN + j;
    float* outB = out + ((size_t)bB * NT) * NN + j;
    const float* dffA = g_dff + (size_t)bA * NN + j;
    const float* dffB = g_dff + (size_t)bB * NN + j;
    unsigned* cntA = &g_cntB[bA * 32];
    unsigned* cntB = &g_cntB[bB * 32];
    unsigned* cntMy = isE ? cntA : cntB;

    float dffA_cur = 0.0f, dffB_cur = 0.0f, dffA_nxt = 0.0f, dffB_nxt = 0.0f;
    if (isE) { dffA_cur = __ldg(dffA); dffB_cur = __ldg(dffB); }

    for (int t = 0; t < NT; ++t) {
        const int p = t & 1;

        // ---- 0. poll own batch (released during the PREVIOUS iteration's
        //         opposite phase -> nearly always satisfied) ----
        if (t > 0) {
            const unsigned target = 128u * (unsigned)t;
            if (lane == 0) {
                unsigned cv;
                do {
                    asm volatile("ld.acquire.gpu.global.u32 %0, [%1];"
                                 : "=r"(cv) : "l"(cntMy));
                } while (cv < target);
            }
            __syncwarp();
        }

        // ---- 1. build lists: E warps -> batch A, I warps -> batch B ----
        unsigned w0 = __ldcg(&g_mask[p][type][bLst][half * 64 + lane]);
        unsigned w1 = __ldcg(&g_mask[p][type][bLst][half * 64 + 32 + lane]);
        int c0 = __popc(w0), c1 = __popc(w1);
        int s0 = c0, s1 = c1;
#pragma unroll
        for (int d = 1; d < 32; d <<= 1) {
            int t0 = __shfl_up_sync(0xffffffffu, s0, d);
            int t1 = __shfl_up_sync(0xffffffffu, s1, d);
            if (lane >= d) { s0 += t0; s1 += t1; }
        }
        int tot0    = __shfl_sync(0xffffffffu, s0, 31);
        int tothalf = tot0 + __shfl_sync(0xffffffffu, s1, 31);
        if (lane == 31) (isE ? s_wsumA : s_wsumB)[slotW] = tothalf;
        __syncthreads();
        {
            const int* ws = isE ? s_wsumA : s_wsumB;
            int base_half = half ? ws[type * 2] : 0;
            unsigned short* dst = isE ? (type ? s_lstAI : s_lstAE)
                                      : (type ? s_lstBI : s_lstBE);
            int pos = base_half + s0 - c0;
            int ib  = (half * 64 + lane) << 5;
            unsigned m = w0;
            while (m) {
                int bit = __ffs(m) - 1; m &= m - 1;
                dst[pos++] = (unsigned short)(ib + bit);
            }
            pos = base_half + tot0 + s1 - c1;
            ib  = (half * 64 + 32 + lane) << 5;
            m = w1;
            while (m) {
                int bit = __ffs(m) - 1; m &= m - 1;
                dst[pos++] = (unsigned short)(ib + bit);
            }
        }
        __syncthreads();
        const int totAE = s_wsumA[0] + s_wsumA[1];
        const int totAI = s_wsumA[2] + s_wsumA[3];
        const int totBE = s_wsumB[0] + s_wsumB[1];
        const int totBI = s_wsumB[2] + s_wsumB[3];

        if (isE && t + 1 < NT) {
            dffA_nxt = __ldg(dffA + (size_t)(t + 1) * (NB * NN));
            dffB_nxt = __ldg(dffB + (size_t)(t + 1) * (NB * NN));
        }

        // ---- 2. gather slot A ----
        float accA = gather_scalar(Wcol, isE ? s_lstAE : s_lstAI,
                                   isE ? totAE : totAI);
        if (!isE) s_accIA[c] = accA;
        __syncthreads();

        // ---- 3. update + publish slot A (E threads; I flow to gather B) ----
        if (isE) {
            float acc_e = accA, acc_i = s_accIA[c];
            hA0 = __fmaf_rn(hA0, C.ar[0], acc_e);
            hA1 = __fmaf_rn(hA1, C.ar[1], __fmul_rn(acc_e, 0.5f));
            hA2 = __fmaf_rn(hA2, C.ar[2], acc_i);
            hA3 = __fmaf_rn(hA3, C.ar[3], dffA_cur);
            qA0 = __fmaf_rn(qA0, C.ad[0], __fmul_rn(C.omad[0], hA0));
            qA1 = __fmaf_rn(qA1, C.ad[1], __fmul_rn(C.omad[1], hA1));
            qA2 = __fmaf_rn(qA2, C.ad[2], __fmul_rn(C.omad[2], hA2));
            qA3 = __fmaf_rn(qA3, C.ad[3], __fmul_rn(C.omad[3], hA3));
            float I = __fmul_rn(qA0, __fsub_rn(C.esyn[0], vA));
            I = __fadd_rn(I, __fmul_rn(qA1, __fsub_rn(C.esyn[1], vA)));
            I = __fadd_rn(I, __fmul_rn(qA2, __fsub_rn(C.esyn[2], vA)));
            I = __fadd_rn(I, __fmul_rn(qA3, __fsub_rn(C.esyn[3], vA)));
            float vn = __fmaf_rn(dtt, __fadd_rn(__fsub_rn(e_l, vA),
                                                __fdiv_rn(I, g_l)), vA);
            bool refr = (refA > 0.0f);
            if (refr) vn = u_reset;
            bool  spk = (!refr) && (vn > theta);
            vA   = spk ? u_reset : vn;
            refA = spk ? refst : fmaxf(__fsub_rn(refA, 1.0f), 0.0f);
            outA[(size_t)t * NN] = spk ? 1.0f : 0.0f;

            unsigned be = __ballot_sync(0xffffffffu, spk && (myct == 0));
            unsigned bi = __ballot_sync(0xffffffffu, spk && (myct == 1));
            if (t != NT - 1 && lane == 0) {
                const int qb = p ^ 1;
                const int word = (cb << 2) + wrp;
                g_mask[qb][0][bA][word] = be;
                g_mask[qb][1][bA][word] = bi;
                asm volatile("red.release.gpu.global.add.u32 [%0], %1;"
                             :: "l"(cntA), "r"(1u) : "memory");
            }
            dffA_cur = dffA_nxt;
        }

        // ---- 4. gather slot B ----
        float accB = gather_scalar(Wcol, isE ? s_lstBE : s_lstBI,
                                   isE ? totBE : totBI);
        if (!isE) s_accIB[c] = accB;
        __syncthreads();

        // ---- 5. update + publish slot B (E threads) ----
        if (isE) {
            float acc_e = accB, acc_i = s_accIB[c];
            hB0 = __fmaf_rn(hB0, C.ar[0], acc_e);
            hB1 = __fmaf_rn(hB1, C.ar[1], __fmul_rn(acc_e, 0.5f));
            hB2 = __fmaf_rn(hB2, C.ar[2], acc_i);
            hB3 = __fmaf_rn(hB3, C.ar[3], dffB_cur);
            qB0 = __fmaf_rn(qB0, C.ad[0], __fmul_rn(C.omad[0], hB0));
            qB1 = __fmaf_rn(qB1, C.ad[1], __fmul_rn(C.omad[1], hB1));
            qB2 = __fmaf_rn(qB2, C.ad[2], __fmul_rn(C.omad[2], hB2));
            qB3 = __fmaf_rn(qB3, C.ad[3], __fmul_rn(C.omad[3], hB3));
            float I = __fmul_rn(qB0, __fsub_rn(C.esyn[0], vB));
            I = __fadd_rn(I, __fmul_rn(qB1, __fsub_rn(C.esyn[1], vB)));
            I = __fadd_rn(I, __fmul_rn(qB2, __fsub_rn(C.esyn[2], vB)));
            I = __fadd_rn(I, __fmul_rn(qB3, __fsub_rn(C.esyn[3], vB)));
            float vn = __fmaf_rn(dtt, __fadd_rn(__fsub_rn(e_l, vB),
                                                __fdiv_rn(I, g_l)), vB);
            bool refr = (refB > 0.0f);
            if (refr) vn = u_reset;
            bool  spk = (!refr) && (vn > theta);
            vB   = spk ? u_reset : vn;
            refB = spk ? refst : fmaxf(__fsub_rn(refB, 1.0f), 0.0f);
            outB[(size_t)t * NN] = spk ? 1.0f : 0.0f;

            unsigned be = __ballot_sync(0xffffffffu, spk && (myct == 0));
            unsigned bi = __ballot_sync(0xffffffffu, spk && (myct == 1));
            if (t != NT - 1 && lane == 0) {
                const int qb = p ^ 1;
                const int word = (cb << 2) + wrp;
                g_mask[qb][0][bB][word] = be;
                g_mask[qb][1][bB][word] = bi;
                asm volatile("red.release.gpu.global.add.u32 [%0], %1;"
                             :: "l"(cntB), "r"(1u) : "memory");
            }
            dffB_cur = dffB_nxt;
        }
    }
}

// ------------------------------------------------------------------
extern "C" void kernel_launch(void* const* d_in, const int* in_sizes, int n_in,
                              void* d_out, int out_size) {
    const float* in_spikes = (const float*)d_in[0];
    const float* weights   = (const float*)d_in[1];
    const float* wff       = (const float*)d_in[2];
    const float* scal      = (const float*)d_in[3];
    const float* scalff    = (const float*)d_in[4];
    const int*   ci        = (const int*)  d_in[5];
    const int*   ciff      = (const int*)  d_in[6];
    float*       out       = (float*)d_out;

    const float tau_rise[4]  = {0.5f, 2.0f, 0.5f, 0.5f};
    const float tau_decay[4] = {2.0f, 100.0f, 5.0f, 2.0f};
    SimConsts C;
    for (int s = 0; s < 4; ++s) {
        float qr = -(0.1f / tau_rise[s]);
        float qd = -(0.1f / tau_decay[s]);
        C.ar[s]   = (float)exp((double)qr);
        C.ad[s]   = (float)exp((double)qd);
        C.omad[s] = 1.0f - C.ad[s];
    }
    C.esyn[0] = 0.0f; C.esyn[1] = 0.0f; C.esyn[2] = -80.0f; C.esyn[3] = 0.0f;
    C.dtt0 = 0.1f / 20.0f;
    C.dtt1 = 0.1f / 10.0f;

    init_kernel<<<8, 256>>>();
    weff_kernel<<<(NN * NN / 4) / 256, 256>>>(weights, scal, ci);
    ff_kernel<<<NT * NB, 256>>>(in_spikes, wff, scalff, ciff, ci);
    sim_kernel<<<SIM_CTAS, SIM_TPB>>>(ci, out, C);
}